// round 15
// baseline (speedup 1.0000x reference)
#include <cuda_runtime.h>
#include <cuda_fp16.h>
#include <cstdint>

#define Bsz 2
#define Lq 4096
#define Dm 512
#define Hh 8
#define Ee 64
#define NC 32
#define CS 128
#define BHn (Bsz*Hh)

// ---------------- scratch ----------------------------------------------------
__device__ float g_loglam[BHn * Lq];
__device__ float g_cum[BHn * Lq];
__device__ float g_q[BHn * Lq * Ee];
__device__ float g_k[BHn * Lq * Ee];
__device__ float g_v[BHn * Lq * Ee];
__device__ float g_S[BHn * NC * Ee * Ee];
__device__ float g_z[BHn * NC * Ee];
__device__ float g_out2[Bsz * Lq * Dm];
__device__ __align__(16) __half g_x16[Bsz * Lq * Dm];
__device__ __align__(16) __half g_a16[Bsz * Lq * Dm];
__device__ __align__(16) __half g_wq_hi[3 * Dm * Dm];
__device__ __align__(16) __half g_wq_lo[3 * Dm * Dm];
__device__ __align__(16) __half g_wo_hi[Dm * Dm];
__device__ __align__(16) __half g_wo_lo[Dm * Dm];

// ---------------- low-level helpers -------------------------------------------
__device__ __forceinline__ uint32_t smem_u32(const void* p) {
    uint32_t a;
    asm("{ .reg .u64 t; cvta.to.shared.u64 t, %1; cvt.u32.u64 %0, t; }" : "=r"(a) : "l"(p));
    return a;
}
__device__ __forceinline__ void ldsm4(uint32_t* r, uint32_t addr) {
    asm volatile("ldmatrix.sync.aligned.m8n8.x4.shared.b16 {%0,%1,%2,%3}, [%4];"
                 : "=r"(r[0]), "=r"(r[1]), "=r"(r[2]), "=r"(r[3]) : "r"(addr));
}
__device__ __forceinline__ void mma16816h(float* d, const uint32_t* a, const uint32_t* b) {
    asm volatile("mma.sync.aligned.m16n8k16.row.col.f32.f16.f16.f32 "
                 "{%0,%1,%2,%3}, {%4,%5,%6,%7}, {%8,%9}, {%0,%1,%2,%3};"
                 : "+f"(d[0]), "+f"(d[1]), "+f"(d[2]), "+f"(d[3])
                 : "r"(a[0]), "r"(a[1]), "r"(a[2]), "r"(a[3]), "r"(b[0]), "r"(b[1]));
}
#define CP_ASYNC16(sm, gm) \
    asm volatile("cp.async.cg.shared.global [%0], [%1], 16;" :: "r"(sm), "l"(gm))
#define CP_COMMIT() asm volatile("cp.async.commit_group;" ::: "memory")
#define CP_WAIT(n)  asm volatile("cp.async.wait_group %0;" :: "n"(n) : "memory")

__device__ __forceinline__ void splitw(float v0, float v1, __half2& ph, __half2& pl) {
    __half h0 = __float2half(v0), h1 = __float2half(v1);
    ph = __halves2half2(h0, h1);
    pl = __halves2half2(__float2half(v0 - __half2float(h0)),
                        __float2half(v1 - __half2float(h1)));
}

// ---------------- K0: fused x->fp16 + decay logits, 2 rows/warp --------------
__global__ __launch_bounds__(256) void split_x_decay_kernel(const float* __restrict__ x,
                                                            const float* __restrict__ dw,
                                                            const float* __restrict__ db) {
    int warp = (blockIdx.x * blockDim.x + threadIdx.x) >> 5;   // 0..4095
    int lane = threadIdx.x & 31;
    int r0 = warp * 2;
    const float4* xr0 = (const float4*)(x + (size_t)r0 * Dm);
    const float4* xr1 = (const float4*)(x + (size_t)(r0 + 1) * Dm);
    float4 xv0[4], xv1[4];
#pragma unroll
    for (int i = 0; i < 4; i++) xv0[i] = xr0[lane + 32 * i];
#pragma unroll
    for (int i = 0; i < 4; i++) xv1[i] = xr1[lane + 32 * i];

    __half2* xo0 = (__half2*)(g_x16 + (size_t)r0 * Dm);
    __half2* xo1 = (__half2*)(g_x16 + (size_t)(r0 + 1) * Dm);
#pragma unroll
    for (int i = 0; i < 4; i++) {
        int idx = lane + 32 * i;
        xo0[2 * idx]     = __floats2half2_rn(xv0[i].x, xv0[i].y);
        xo0[2 * idx + 1] = __floats2half2_rn(xv0[i].z, xv0[i].w);
        xo1[2 * idx]     = __floats2half2_rn(xv1[i].x, xv1[i].y);
        xo1[2 * idx + 1] = __floats2half2_rn(xv1[i].z, xv1[i].w);
    }
    int b = r0 >> 12, l = r0 & 4095;
#pragma unroll
    for (int h = 0; h < Hh; h++) {
        const float4* wr = (const float4*)(dw + (size_t)h * Dm);
        float p0 = 0.f, p1 = 0.f;
#pragma unroll
        for (int i = 0; i < 4; i++) {
            float4 w = wr[lane + 32 * i];
            p0 += xv0[i].x * w.x + xv0[i].y * w.y + xv0[i].z * w.z + xv0[i].w * w.w;
            p1 += xv1[i].x * w.x + xv1[i].y * w.y + xv1[i].z * w.z + xv1[i].w * w.w;
        }
#pragma unroll
        for (int o = 16; o; o >>= 1) {
            p0 += __shfl_xor_sync(0xffffffffu, p0, o);
            p1 += __shfl_xor_sync(0xffffffffu, p1, o);
        }
        if (lane == 0) {
            float lam0 = fmaxf(0.9f + 0.1f / (1.f + expf(-(p0 + db[h]))), 1e-6f);
            float lam1 = fmaxf(0.9f + 0.1f / (1.f + expf(-(p1 + db[h]))), 1e-6f);
            size_t base = ((size_t)(b * Hh + h)) * Lq + l;
            g_loglam[base] = logf(lam0);
            g_loglam[base + 1] = logf(lam1);
        }
    }
}

// ---------------- K0w: both weight splits (fp16 hi/lo) in one launch ---------
__global__ void split_w_kernel(const float* __restrict__ qkv_w,
                               const float* __restrict__ out_w) {
    int i = blockIdx.x * blockDim.x + threadIdx.x;
    const int nq = 3 * Dm * Dm / 4;
    const float* s; __half *hi, *lo; int j;
    if (i < nq) { s = qkv_w; hi = g_wq_hi; lo = g_wq_lo; j = i; }
    else {
        j = i - nq;
        if (j >= Dm * Dm / 4) return;
        s = out_w; hi = g_wo_hi; lo = g_wo_lo;
    }
    float4 v = ((const float4*)s)[j];
    __half2 ph0, pl0, ph1, pl1;
    splitw(v.x, v.y, ph0, pl0);
    splitw(v.z, v.w, ph1, pl1);
    ((__half2*)hi)[2 * j] = ph0; ((__half2*)hi)[2 * j + 1] = ph1;
    ((__half2*)lo)[2 * j] = pl0; ((__half2*)lo)[2 * j + 1] = pl1;
}

// ---------------- K0b: inclusive scan of log lambda per (b,h), clip ----------
__global__ void cum_scan_kernel() {
    int bh = blockIdx.x;
    int tid = threadIdx.x;
    int lane = tid & 31, w = tid >> 5;
    const float* src = g_loglam + (size_t)bh * Lq + tid * 8;
    float v[8]; float s = 0.f;
#pragma unroll
    for (int j = 0; j < 8; j++) { v[j] = src[j]; s += v[j]; }
    float sc = s;
#pragma unroll
    for (int o = 1; o < 32; o <<= 1) {
        float n = __shfl_up_sync(0xffffffffu, sc, o);
        if (lane >= o) sc += n;
    }
    __shared__ float wt[16];
    if (lane == 31) wt[w] = sc;
    __syncthreads();
    if (tid < 16) {
        float ws = wt[tid];
#pragma unroll
        for (int o = 1; o < 16; o <<= 1) {
            float n = __shfl_up_sync(0xffffu, ws, o);
            if (tid >= o) ws += n;
        }
        wt[tid] = ws;
    }
    __syncthreads();
    float base = ((w > 0) ? wt[w - 1] : 0.f) + sc - s;
    float run = base;
    float* dst = g_cum + (size_t)bh * Lq + tid * 8;
#pragma unroll
    for (int j = 0; j < 8; j++) {
        run += v[j];
        dst[j] = fminf(fmaxf(run, -50.f), 50.f);
    }
}

// ---------------- HMMA GEMM fp16: C = A·(Wh+Wl)^T, 128x64 tile ---------------
// BK=64 (8 k-iterations), 2-stage cp.async pipeline, 32 KB/stage, occ 3.
// smem row = 128 B (8 granules), swizzle g' = g ^ (row & 7).
template <int EPI>
__global__ __launch_bounds__(256, 3) void gemm_mma_kernel(const float* __restrict__ bias) {
    extern __shared__ __align__(16) char dynsmem[];
    constexpr int KD = 512, BK = 64, NKB = KD / BK;    // 8 k-blocks
    constexpr int WOFF = 16384, WLOFF = 24576;
    constexpr int STAGEB = 32768;
    uint32_t sb0 = smem_u32(dynsmem);

    int tid = threadIdx.x;
    int warp = tid >> 5, lane = tid & 31;
    int warp_m = warp & 3, warp_n = warp >> 2;
    int m0 = blockIdx.y * 128, n0 = blockIdx.x * 64;

    const __half* A  = (EPI ? g_x16 : g_a16) + (size_t)m0 * KD;
    const __half* Wh = (EPI ? g_wq_hi : g_wo_hi) + (size_t)n0 * KD;
    const __half* Wl = (EPI ? g_wq_lo : g_wo_lo) + (size_t)n0 * KD;

    float acc[32];
#pragma unroll
    for (int i = 0; i < 32; i++) acc[i] = 0.f;

    auto load_stage = [&](int st, int kb) {
        uint32_t base = sb0 + (uint32_t)(st * STAGEB);
        // A: 128 rows x 8 granules = 1024
#pragma unroll
        for (int it = 0; it < 4; it++) {
            int q = tid + it * 256;
            int row = q >> 3, g = q & 7;
            uint32_t dst = base + (uint32_t)(row * 128 + ((g ^ (row & 7)) << 4));
            CP_ASYNC16(dst, A + (size_t)row * KD + kb * BK + g * 8);
        }
        // Wh / Wl: 64 rows x 8 granules = 512 each
#pragma unroll
        for (int it = 0; it < 2; it++) {
            int q = tid + it * 256;
            int row = q >> 3, g = q & 7;
            uint32_t sw = (uint32_t)(row * 128 + ((g ^ (row & 7)) << 4));
            CP_ASYNC16(base + WOFF + sw, Wh + (size_t)row * KD + kb * BK + g * 8);
            CP_ASYNC16(base + WLOFF + sw, Wl + (size_t)row * KD + kb * BK + g * 8);
        }
        CP_COMMIT();
    };

    load_stage(0, 0);
    for (int kb = 0; kb < NKB; kb++) {
        CP_WAIT(0);
        __syncthreads();
        if (kb + 1 < NKB) load_stage((kb + 1) & 1, kb + 1);
        uint32_t st = sb0 + (uint32_t)((kb & 1) * STAGEB);
#pragma unroll
        for (int ks = 0; ks < 4; ks++) {
            uint32_t af[2][4];
#pragma unroll
            for (int im = 0; im < 2; im++) {
                int row = warp_m * 32 + im * 16 + (lane & 7) + ((lane >> 3) & 1) * 8;
                int gc = ks * 2 + (lane >> 4);
                uint32_t sw = (uint32_t)(row * 128 + ((gc ^ (row & 7)) << 4));
                ldsm4(af[im], st + sw);
            }
#pragma unroll
            for (int jn2 = 0; jn2 < 2; jn2++) {
                uint32_t bfh[4], bfl[4];
                int rowb = warp_n * 32 + jn2 * 16 + (lane & 7) + (lane >> 4) * 8;
                int gcb = ks * 2 + ((lane >> 3) & 1);
                uint32_t swb = (uint32_t)(rowb * 128 + ((gcb ^ (rowb & 7)) << 4));
                ldsm4(bfh, st + WOFF + swb);
                ldsm4(bfl, st + WLOFF + swb);
#pragma unroll
                for (int im = 0; im < 2; im++) {
#pragma unroll
                    for (int na = 0; na < 2; na++) {
                        float* d = &acc[(im * 4 + jn2 * 2 + na) * 4];
                        mma16816h(d, af[im], bfh + na * 2);
                        mma16816h(d, af[im], bfl + na * 2);
                    }
                }
            }
        }
    }
    __syncthreads();

    float* Csm = (float*)dynsmem;
    {
        int r0 = warp_m * 32 + (lane >> 2);
        int c0 = warp_n * 32 + (lane & 3) * 2;
#pragma unroll
        for (int im = 0; im < 2; im++) {
#pragma unroll
            for (int jn = 0; jn < 4; jn++) {
                float* d = &acc[(im * 4 + jn) * 4];
                int rr = r0 + im * 16, cc = c0 + jn * 8;
                Csm[rr * 68 + cc] = d[0];
                Csm[rr * 68 + cc + 1] = d[1];
                Csm[(rr + 8) * 68 + cc] = d[2];
                Csm[(rr + 8) * 68 + cc + 1] = d[3];
            }
        }
    }
    __syncthreads();

    int sec = 0, h0 = 0;
    if (EPI == 1) { sec = n0 >> 9; h0 = (n0 & 511) >> 6; }
#pragma unroll 4
    for (int it = 0; it < 32; it++) {
        int idx = it * 256 + tid;
        int row = idx >> 6, col = idx & 63;
        float val = Csm[row * 68 + col] + bias[n0 + col];
        int m = m0 + row;
        if (EPI == 0) {
            g_out2[(size_t)m * Dm + n0 + col] = val;
        } else {
            int b = m >> 12, l = m & 4095;
            size_t rowoff = ((size_t)(b * Hh + h0) * Lq + l) * Ee + col;
            if (sec == 2) {
                g_v[rowoff] = val;
            } else {
                float cum = g_cum[(size_t)(b * Hh + h0) * Lq + l];
                float mul = (sec == 0) ? 0.125f * expf(cum) : expf(-cum);
                float fm = (val > 0.f) ? val + 1.f : expf(val);
                ((sec == 0) ? g_q : g_k)[rowoff] = fm * mul;
            }
        }
    }
}

// ---------------- K2: per-chunk S = KᵀV (64x64), z = Σk, cp.async pipeline ---
__global__ __launch_bounds__(256) void chunk_sum_kernel() {
    __shared__ __align__(16) float Ks[2][32 * Ee];
    __shared__ __align__(16) float Vs[2][32 * Ee];
    int blk = blockIdx.x;
    int c = blk & (NC - 1);
    int bh = blk >> 5;
    int tid = threadIdx.x;
    int tx = tid & 15, ty = tid >> 4;
    const float* Kb = g_k + ((size_t)bh * Lq + c * CS) * Ee;
    const float* Vb = g_v + ((size_t)bh * Lq + c * CS) * Ee;
    uint32_t ksb = smem_u32(Ks), vsb = smem_u32(Vs);

    auto prefetch = [&](int st, int r0) {
#pragma unroll
        for (int u = 0; u < 2; u++) {
            int idx = tid + u * 256;
            CP_ASYNC16(ksb + (uint32_t)(st * 8192 + idx * 16),
                       (const float4*)(Kb + r0 * Ee) + idx);
            CP_ASYNC16(vsb + (uint32_t)(st * 8192 + idx * 16),
                       (const float4*)(Vb + r0 * Ee) + idx);
        }
        CP_COMMIT();
    };
    prefetch(0, 0);

    float acc[4][4];
#pragma unroll
    for (int i = 0; i < 4; i++)
#pragma unroll
        for (int j = 0; j < 4; j++) acc[i][j] = 0.f;
    float zacc[4] = {0.f, 0.f, 0.f, 0.f};

    for (int t0 = 0; t0 < 4; t0++) {
        CP_WAIT(0);
        __syncthreads();
        if (t0 + 1 < 4) prefetch((t0 + 1) & 1, (t0 + 1) * 32);
        const float* Kt = Ks[t0 & 1];
        const float* Vt = Vs[t0 & 1];
#pragma unroll
        for (int r = 0; r < 32; r++) {
            float a[4], bq[4];
#pragma unroll
            for (int i = 0; i < 4; i++) a[i] = Kt[r * Ee + ty * 4 + i];
#pragma unroll
            for (int j = 0; j < 4; j++) bq[j] = Vt[r * Ee + tx * 4 + j];
#pragma unroll
            for (int i = 0; i < 4; i++) {
                zacc[i] += a[i];
#pragma unroll
                for (int j = 0; j < 4; j++) acc[i][j] += a[i] * bq[j];
            }
        }
    }
    float* Sd = g_S + (size_t)blk * Ee * Ee;
#pragma unroll
    for (int i = 0; i < 4; i++)
#pragma unroll
        for (int j = 0; j < 4; j++) Sd[(ty * 4 + i) * Ee + tx * 4 + j] = acc[i][j];
    if (tx == 0) {
        float* zd = g_z + (size_t)blk * Ee;
#pragma unroll
        for (int i = 0; i < 4; i++) zd[ty * 4 + i] = zacc[i];
    }
}

// ---------------- K3: exclusive prefix over chunks (full-width grid) ---------
__global__ __launch_bounds__(512) void chunk_prefix_kernel() {
    int bh = blockIdx.x;
    int idx = blockIdx.y * 512 + threadIdx.x;
    float* p = g_S + (size_t)bh * NC * (Ee * Ee) + idx;
    float v[NC];
#pragma unroll
    for (int c = 0; c < NC; c++) v[c] = p[(size_t)c * (Ee * Ee)];
    float carry = 0.f;
#pragma unroll
    for (int c = 0; c < NC; c++) { p[(size_t)c * (Ee * Ee)] = carry; carry += v[c]; }
    if (blockIdx.y == 0 && threadIdx.x < Ee) {
        float* pz = g_z + (size_t)bh * NC * Ee + threadIdx.x;
        float zv[NC];
#pragma unroll
        for (int c = 0; c < NC; c++) zv[c] = pz[c * Ee];
        float zc = 0.f;
#pragma unroll
        for (int c = 0; c < NC; c++) { pz[c * Ee] = zc; zc += zv[c]; }
    }
}

// ---------------- K4: chunked causal linear attention (fp16 out) -------------
__global__ __launch_bounds__(128) void attn_kernel() {
    __shared__ float sh[Ee * Ee + Ee];
    int blk = blockIdx.x;
    int c = blk & 31;
    int bh = blk >> 5;
    int t = threadIdx.x;
    const float* qp = g_q + ((size_t)bh * Lq + c * CS + t) * Ee;
    float q[Ee];
#pragma unroll
    for (int i = 0; i < 16; i++) {
        float4 v4 = ((const float4*)qp)[i];
        q[4 * i] = v4.x; q[4 * i + 1] = v4.y; q[4 * i + 2] = v4.z; q[4 * i + 3] = v4.w;
    }
    const float* Sp = g_S + (size_t)blk * Ee * Ee;
#pragma unroll
    for (int u = 0; u < 8; u++) ((float4*)sh)[t + u * 128] = ((const float4*)Sp)[t + u * 128];
    if (t < 16) ((float4*)(sh + Ee * Ee))[t] = ((const float4*)(g_z + (size_t)blk * Ee))[t];
    __syncthreads();

    float num[Ee];
#pragma unroll
    for (int f = 0; f < Ee; f++) num[f] = 0.f;
    float den = 1e-6f;
#pragma unroll
    for (int e = 0; e < Ee; e++) {
        float qe = q[e];
        den += qe * sh[Ee * Ee + e];
        const float4* srow = (const float4*)(sh + e * Ee);
#pragma unroll
        for (int f4 = 0; f4 < 16; f4++) {
            float4 sv = srow[f4];
            num[4 * f4]     += qe * sv.x;
            num[4 * f4 + 1] += qe * sv.y;
            num[4 * f4 + 2] += qe * sv.z;
            num[4 * f4 + 3] += qe * sv.w;
        }
    }
    __syncthreads();

    const float* Kb = g_k + ((size_t)bh * Lq + c * CS) * Ee;
    const float* Vb = g_v + ((size_t)bh * Lq + c * CS) * Ee;
    for (int s0 = 0; s0 < CS; s0 += 32) {
#pragma unroll
        for (int u = 0; u < 4; u++) {
            int idx = t + u * 128;
            ((float4*)sh)[idx] = ((const float4*)(Kb + s0 * Ee))[idx];
            ((float4*)(sh + 2048))[idx] = ((const float4*)(Vb + s0 * Ee))[idx];
        }
        __syncthreads();
        for (int s = 0; s < 32; s++) {
            if (s0 + s <= t) {
                float a = 0.f;
                const float4* krow = (const float4*)(sh + s * Ee);
#pragma unroll
                for (int e4 = 0; e4 < 16; e4++) {
                    float4 kv = krow[e4];
                    a += q[4 * e4] * kv.x + q[4 * e4 + 1] * kv.y
                       + q[4 * e4 + 2] * kv.z + q[4 * e4 + 3] * kv.w;
                }
                den += a;
                const float4* vrow = (const float4*)(sh + 2048 + s * Ee);
#pragma unroll
                for (int f4 = 0; f4 < 16; f4++) {
                    float4 vv = vrow[f4];
                    num[4 * f4]     += a * vv.x;
                    num[4 * f4 + 1] += a * vv.y;
                    num[4 * f4 + 2] += a * vv.z;
                    num[4 * f4 + 3] += a * vv.w;
                }
            }
        }
        __syncthreads();
    }
    float invd = 1.0f / den;
    int b = bh >> 3, h = bh & 7;
    size_t off = ((size_t)(b * Lq + c * CS + t)) * Dm + h * Ee;
    __half2* oh = (__half2*)(g_a16 + off);
#pragma unroll
    for (int f2 = 0; f2 < 32; f2++)
        oh[f2] = __floats2half2_rn(num[2 * f2] * invd, num[2 * f2 + 1] * invd);
}

// ---------------- K6: RMSNorm, warp-per-row -----------------------------------
__global__ __launch_bounds__(256) void rmsnorm_kernel(const float* __restrict__ scale,
                                                      float* __restrict__ out) {
    int w = (blockIdx.x * blockDim.x + threadIdx.x) >> 5;   // row 0..8191
    int lane = threadIdx.x & 31;
    const float4* r = (const float4*)(g_out2 + (size_t)w * Dm);
    float4 v[4];
    float ss = 0.f;
#pragma unroll
    for (int i = 0; i < 4; i++) {
        v[i] = r[lane + 32 * i];
        ss += v[i].x * v[i].x + v[i].y * v[i].y + v[i].z * v[i].z + v[i].w * v[i].w;
    }
#pragma unroll
    for (int o = 16; o; o >>= 1) ss += __shfl_xor_sync(0xffffffffu, ss, o);
    float rn = rsqrtf(ss * (1.0f / 512.0f) + 1e-8f);
    const float4* sc = (const float4*)scale;
    float4* od = (float4*)(out + (size_t)w * Dm);
#pragma unroll
    for (int i = 0; i < 4; i++) {
        float4 s4 = sc[lane + 32 * i];
        float4 o4;
        o4.x = v[i].x * rn * s4.x; o4.y = v[i].y * rn * s4.y;
        o4.z = v[i].z * rn * s4.z; o4.w = v[i].w * rn * s4.w;
        od[lane + 32 * i] = o4;
    }
}

// ---------------- launch ------------------------------------------------------
extern "C" void kernel_launch(void* const* d_in, const int* in_sizes, int n_in,
                              void* d_out, int out_size) {
    const float* x          = (const float*)d_in[0];
    const float* qkv_w      = (const float*)d_in[1];
    const float* qkv_b      = (const float*)d_in[2];
    const float* out_w      = (const float*)d_in[3];
    const float* out_b      = (const float*)d_in[4];
    const float* decay_w    = (const float*)d_in[5];
    const float* decay_b    = (const float*)d_in[6];
    const float* norm_scale = (const float*)d_in[7];
    float* out = (float*)d_out;
    (void)in_sizes; (void)n_in; (void)out_size;

    // dynamic smem: max(2 stages x 32 KB = 65536, C staging 34816)
    const int DYN = 65536;
    static bool attr_set = false;
    if (!attr_set) {
        cudaFuncSetAttribute(gemm_mma_kernel<1>, cudaFuncAttributeMaxDynamicSharedMemorySize, DYN);
        cudaFuncSetAttribute(gemm_mma_kernel<0>, cudaFuncAttributeMaxDynamicSharedMemorySize, DYN);
        attr_set = true;
    }

    split_w_kernel<<<1024, 256>>>(qkv_w, out_w);
    split_x_decay_kernel<<<512, 256>>>(x, decay_w, decay_b);
    cum_scan_kernel<<<BHn, 512>>>();

    gemm_mma_kernel<1><<<dim3(24, 64), 256, DYN>>>(qkv_b);

    chunk_sum_kernel<<<BHn * NC, 256>>>();
    chunk_prefix_kernel<<<dim3(BHn, 8), 512>>>();
    attn_kernel<<<BHn * NC, 128>>>();

    gemm_mma_kernel<0><<<dim3(8, 64), 256, DYN>>>(out_b);

    rmsnorm_kernel<<<1024, 256>>>(norm_scale, out);
}

// round 16
// speedup vs baseline: 1.0403x; 1.0403x over previous
#include <cuda_runtime.h>
#include <cuda_fp16.h>
#include <cstdint>

#define Bsz 2
#define Lq 4096
#define Dm 512
#define Hh 8
#define Ee 64
#define NC 32
#define CS 128
#define BHn (Bsz*Hh)

// ---------------- scratch ----------------------------------------------------
__device__ float g_loglam[BHn * Lq];
__device__ float g_cum[BHn * Lq];
__device__ float g_q[BHn * Lq * Ee];
__device__ float g_k[BHn * Lq * Ee];
__device__ float g_v[BHn * Lq * Ee];
__device__ float g_S[BHn * NC * Ee * Ee];
__device__ float g_z[BHn * NC * Ee];
__device__ float g_out2[Bsz * Lq * Dm];
__device__ __align__(16) __half g_x16[Bsz * Lq * Dm];
__device__ __align__(16) __half g_a16[Bsz * Lq * Dm];
__device__ __align__(16) __half g_wq_hi[3 * Dm * Dm];
__device__ __align__(16) __half g_wq_lo[3 * Dm * Dm];
__device__ __align__(16) __half g_wo_hi[Dm * Dm];
__device__ __align__(16) __half g_wo_lo[Dm * Dm];

// ---------------- low-level helpers -------------------------------------------
__device__ __forceinline__ uint32_t smem_u32(const void* p) {
    uint32_t a;
    asm("{ .reg .u64 t; cvta.to.shared.u64 t, %1; cvt.u32.u64 %0, t; }" : "=r"(a) : "l"(p));
    return a;
}
__device__ __forceinline__ void ldsm4(uint32_t* r, uint32_t addr) {
    asm volatile("ldmatrix.sync.aligned.m8n8.x4.shared.b16 {%0,%1,%2,%3}, [%4];"
                 : "=r"(r[0]), "=r"(r[1]), "=r"(r[2]), "=r"(r[3]) : "r"(addr));
}
__device__ __forceinline__ void mma16816h(float* d, const uint32_t* a, const uint32_t* b) {
    asm volatile("mma.sync.aligned.m16n8k16.row.col.f32.f16.f16.f32 "
                 "{%0,%1,%2,%3}, {%4,%5,%6,%7}, {%8,%9}, {%0,%1,%2,%3};"
                 : "+f"(d[0]), "+f"(d[1]), "+f"(d[2]), "+f"(d[3])
                 : "r"(a[0]), "r"(a[1]), "r"(a[2]), "r"(a[3]), "r"(b[0]), "r"(b[1]));
}
#define CP_ASYNC16(sm, gm) \
    asm volatile("cp.async.cg.shared.global [%0], [%1], 16;" :: "r"(sm), "l"(gm))
#define CP_COMMIT() asm volatile("cp.async.commit_group;" ::: "memory")
#define CP_WAIT(n)  asm volatile("cp.async.wait_group %0;" :: "n"(n) : "memory")

__device__ __forceinline__ void splitw(float v0, float v1, __half2& ph, __half2& pl) {
    __half h0 = __float2half(v0), h1 = __float2half(v1);
    ph = __halves2half2(h0, h1);
    pl = __halves2half2(__float2half(v0 - __half2float(h0)),
                        __float2half(v1 - __half2float(h1)));
}

// ---------------- K0: fused x->fp16 + decay logits, 2 rows/warp --------------
__global__ __launch_bounds__(256) void split_x_decay_kernel(const float* __restrict__ x,
                                                            const float* __restrict__ dw,
                                                            const float* __restrict__ db) {
    int warp = (blockIdx.x * blockDim.x + threadIdx.x) >> 5;   // 0..4095
    int lane = threadIdx.x & 31;
    int r0 = warp * 2;
    const float4* xr0 = (const float4*)(x + (size_t)r0 * Dm);
    const float4* xr1 = (const float4*)(x + (size_t)(r0 + 1) * Dm);
    float4 xv0[4], xv1[4];
#pragma unroll
    for (int i = 0; i < 4; i++) xv0[i] = xr0[lane + 32 * i];
#pragma unroll
    for (int i = 0; i < 4; i++) xv1[i] = xr1[lane + 32 * i];

    __half2* xo0 = (__half2*)(g_x16 + (size_t)r0 * Dm);
    __half2* xo1 = (__half2*)(g_x16 + (size_t)(r0 + 1) * Dm);
#pragma unroll
    for (int i = 0; i < 4; i++) {
        int idx = lane + 32 * i;
        xo0[2 * idx]     = __floats2half2_rn(xv0[i].x, xv0[i].y);
        xo0[2 * idx + 1] = __floats2half2_rn(xv0[i].z, xv0[i].w);
        xo1[2 * idx]     = __floats2half2_rn(xv1[i].x, xv1[i].y);
        xo1[2 * idx + 1] = __floats2half2_rn(xv1[i].z, xv1[i].w);
    }
    int b = r0 >> 12, l = r0 & 4095;
#pragma unroll
    for (int h = 0; h < Hh; h++) {
        const float4* wr = (const float4*)(dw + (size_t)h * Dm);
        float p0 = 0.f, p1 = 0.f;
#pragma unroll
        for (int i = 0; i < 4; i++) {
            float4 w = wr[lane + 32 * i];
            p0 += xv0[i].x * w.x + xv0[i].y * w.y + xv0[i].z * w.z + xv0[i].w * w.w;
            p1 += xv1[i].x * w.x + xv1[i].y * w.y + xv1[i].z * w.z + xv1[i].w * w.w;
        }
#pragma unroll
        for (int o = 16; o; o >>= 1) {
            p0 += __shfl_xor_sync(0xffffffffu, p0, o);
            p1 += __shfl_xor_sync(0xffffffffu, p1, o);
        }
        if (lane == 0) {
            float lam0 = fmaxf(0.9f + 0.1f / (1.f + expf(-(p0 + db[h]))), 1e-6f);
            float lam1 = fmaxf(0.9f + 0.1f / (1.f + expf(-(p1 + db[h]))), 1e-6f);
            size_t base = ((size_t)(b * Hh + h)) * Lq + l;
            g_loglam[base] = logf(lam0);
            g_loglam[base + 1] = logf(lam1);
        }
    }
}

// ---------------- K0w: both weight splits (fp16 hi/lo) in one launch ---------
__global__ void split_w_kernel(const float* __restrict__ qkv_w,
                               const float* __restrict__ out_w) {
    int i = blockIdx.x * blockDim.x + threadIdx.x;
    const int nq = 3 * Dm * Dm / 4;
    const float* s; __half *hi, *lo; int j;
    if (i < nq) { s = qkv_w; hi = g_wq_hi; lo = g_wq_lo; j = i; }
    else {
        j = i - nq;
        if (j >= Dm * Dm / 4) return;
        s = out_w; hi = g_wo_hi; lo = g_wo_lo;
    }
    float4 v = ((const float4*)s)[j];
    __half2 ph0, pl0, ph1, pl1;
    splitw(v.x, v.y, ph0, pl0);
    splitw(v.z, v.w, ph1, pl1);
    ((__half2*)hi)[2 * j] = ph0; ((__half2*)hi)[2 * j + 1] = ph1;
    ((__half2*)lo)[2 * j] = pl0; ((__half2*)lo)[2 * j + 1] = pl1;
}

// ---------------- K0b: inclusive scan of log lambda per (b,h), clip ----------
__global__ void cum_scan_kernel() {
    int bh = blockIdx.x;
    int tid = threadIdx.x;
    int lane = tid & 31, w = tid >> 5;
    const float* src = g_loglam + (size_t)bh * Lq + tid * 8;
    float v[8]; float s = 0.f;
#pragma unroll
    for (int j = 0; j < 8; j++) { v[j] = src[j]; s += v[j]; }
    float sc = s;
#pragma unroll
    for (int o = 1; o < 32; o <<= 1) {
        float n = __shfl_up_sync(0xffffffffu, sc, o);
        if (lane >= o) sc += n;
    }
    __shared__ float wt[16];
    if (lane == 31) wt[w] = sc;
    __syncthreads();
    if (tid < 16) {
        float ws = wt[tid];
#pragma unroll
        for (int o = 1; o < 16; o <<= 1) {
            float n = __shfl_up_sync(0xffffu, ws, o);
            if (tid >= o) ws += n;
        }
        wt[tid] = ws;
    }
    __syncthreads();
    float base = ((w > 0) ? wt[w - 1] : 0.f) + sc - s;
    float run = base;
    float* dst = g_cum + (size_t)bh * Lq + tid * 8;
#pragma unroll
    for (int j = 0; j < 8; j++) {
        run += v[j];
        dst[j] = fminf(fmaxf(run, -50.f), 50.f);
    }
}

// ---------------- HMMA GEMM fp16 (R14 config: BK=32, 3 stages, occ 3) --------
template <int EPI>
__global__ __launch_bounds__(256, 3) void gemm_mma_kernel(const float* __restrict__ bias) {
    extern __shared__ __align__(16) char dynsmem[];
    constexpr int KD = 512, BK = 32, NKB = KD / BK;
    constexpr int WOFF = 8192, WLOFF = 12288;
    constexpr int STAGEB = 16384;
    uint32_t sb0 = smem_u32(dynsmem);

    int tid = threadIdx.x;
    int warp = tid >> 5, lane = tid & 31;
    int warp_m = warp & 3, warp_n = warp >> 2;
    int m0 = blockIdx.y * 128, n0 = blockIdx.x * 64;

    const __half* A  = (EPI ? g_x16 : g_a16) + (size_t)m0 * KD;
    const __half* Wh = (EPI ? g_wq_hi : g_wo_hi) + (size_t)n0 * KD;
    const __half* Wl = (EPI ? g_wq_lo : g_wo_lo) + (size_t)n0 * KD;

    float acc[32];
#pragma unroll
    for (int i = 0; i < 32; i++) acc[i] = 0.f;

    auto load_stage = [&](int st, int kb) {
        uint32_t base = sb0 + (uint32_t)(st * STAGEB);
#pragma unroll
        for (int it = 0; it < 2; it++) {
            int q = tid + it * 256;
            int row = q >> 2, g = q & 3;
            uint32_t dst = base + (uint32_t)(row * 64 + ((g ^ ((row >> 1) & 3)) << 4));
            CP_ASYNC16(dst, A + (size_t)row * KD + kb * BK + g * 8);
        }
        {
            int row = tid >> 2, g = tid & 3;
            uint32_t sw = (uint32_t)(row * 64 + ((g ^ ((row >> 1) & 3)) << 4));
            CP_ASYNC16(base + WOFF + sw, Wh + (size_t)row * KD + kb * BK + g * 8);
            CP_ASYNC16(base + WLOFF + sw, Wl + (size_t)row * KD + kb * BK + g * 8);
        }
        CP_COMMIT();
    };

    load_stage(0, 0);
    load_stage(1, 1);
    for (int kb = 0; kb < NKB; kb++) {
        if (kb + 1 < NKB) CP_WAIT(1); else CP_WAIT(0);
        __syncthreads();
        if (kb + 2 < NKB) load_stage((kb + 2) % 3, kb + 2);
        uint32_t st = sb0 + (uint32_t)((kb % 3) * STAGEB);
#pragma unroll
        for (int ks = 0; ks < 2; ks++) {
            uint32_t af[2][4];
#pragma unroll
            for (int im = 0; im < 2; im++) {
                int row = warp_m * 32 + im * 16 + (lane & 7) + ((lane >> 3) & 1) * 8;
                int gc = ks * 2 + (lane >> 4);
                uint32_t sw = (uint32_t)(row * 64 + ((gc ^ ((row >> 1) & 3)) << 4));
                ldsm4(af[im], st + sw);
            }
#pragma unroll
            for (int jn2 = 0; jn2 < 2; jn2++) {
                uint32_t bfh[4], bfl[4];
                int rowb = warp_n * 32 + jn2 * 16 + (lane & 7) + (lane >> 4) * 8;
                int gcb = ks * 2 + ((lane >> 3) & 1);
                uint32_t swb = (uint32_t)(rowb * 64 + ((gcb ^ ((rowb >> 1) & 3)) << 4));
                ldsm4(bfh, st + WOFF + swb);
                ldsm4(bfl, st + WLOFF + swb);
#pragma unroll
                for (int im = 0; im < 2; im++) {
#pragma unroll
                    for (int na = 0; na < 2; na++) {
                        float* d = &acc[(im * 4 + jn2 * 2 + na) * 4];
                        mma16816h(d, af[im], bfh + na * 2);
                        mma16816h(d, af[im], bfl + na * 2);
                    }
                }
            }
        }
    }
    __syncthreads();

    float* Csm = (float*)dynsmem;
    {
        int r0 = warp_m * 32 + (lane >> 2);
        int c0 = warp_n * 32 + (lane & 3) * 2;
#pragma unroll
        for (int im = 0; im < 2; im++) {
#pragma unroll
            for (int jn = 0; jn < 4; jn++) {
                float* d = &acc[(im * 4 + jn) * 4];
                int rr = r0 + im * 16, cc = c0 + jn * 8;
                Csm[rr * 68 + cc] = d[0];
                Csm[rr * 68 + cc + 1] = d[1];
                Csm[(rr + 8) * 68 + cc] = d[2];
                Csm[(rr + 8) * 68 + cc + 1] = d[3];
            }
        }
    }
    __syncthreads();

    int sec = 0, h0 = 0;
    if (EPI == 1) { sec = n0 >> 9; h0 = (n0 & 511) >> 6; }
#pragma unroll 4
    for (int it = 0; it < 32; it++) {
        int idx = it * 256 + tid;
        int row = idx >> 6, col = idx & 63;
        float val = Csm[row * 68 + col] + bias[n0 + col];
        int m = m0 + row;
        if (EPI == 0) {
            g_out2[(size_t)m * Dm + n0 + col] = val;
        } else {
            int b = m >> 12, l = m & 4095;
            size_t rowoff = ((size_t)(b * Hh + h0) * Lq + l) * Ee + col;
            if (sec == 2) {
                g_v[rowoff] = val;
            } else {
                float cum = g_cum[(size_t)(b * Hh + h0) * Lq + l];
                float mul = (sec == 0) ? 0.125f * expf(cum) : expf(-cum);
                float fm = (val > 0.f) ? val + 1.f : expf(val);
                ((sec == 0) ? g_q : g_k)[rowoff] = fm * mul;
            }
        }
    }
}

// ---------------- K2: per-chunk S = KᵀV (64x64), z = Σk, cp.async pipeline ---
__global__ __launch_bounds__(256) void chunk_sum_kernel() {
    __shared__ __align__(16) float Ks[2][32 * Ee];
    __shared__ __align__(16) float Vs[2][32 * Ee];
    int blk = blockIdx.x;
    int c = blk & (NC - 1);
    int bh = blk >> 5;
    int tid = threadIdx.x;
    int tx = tid & 15, ty = tid >> 4;
    const float* Kb = g_k + ((size_t)bh * Lq + c * CS) * Ee;
    const float* Vb = g_v + ((size_t)bh * Lq + c * CS) * Ee;
    uint32_t ksb = smem_u32(Ks), vsb = smem_u32(Vs);

    auto prefetch = [&](int st, int r0) {
#pragma unroll
        for (int u = 0; u < 2; u++) {
            int idx = tid + u * 256;
            CP_ASYNC16(ksb + (uint32_t)(st * 8192 + idx * 16),
                       (const float4*)(Kb + r0 * Ee) + idx);
            CP_ASYNC16(vsb + (uint32_t)(st * 8192 + idx * 16),
                       (const float4*)(Vb + r0 * Ee) + idx);
        }
        CP_COMMIT();
    };
    prefetch(0, 0);

    float acc[4][4];
#pragma unroll
    for (int i = 0; i < 4; i++)
#pragma unroll
        for (int j = 0; j < 4; j++) acc[i][j] = 0.f;
    float zacc[4] = {0.f, 0.f, 0.f, 0.f};

    for (int t0 = 0; t0 < 4; t0++) {
        CP_WAIT(0);
        __syncthreads();
        if (t0 + 1 < 4) prefetch((t0 + 1) & 1, (t0 + 1) * 32);
        const float* Kt = Ks[t0 & 1];
        const float* Vt = Vs[t0 & 1];
#pragma unroll
        for (int r = 0; r < 32; r++) {
            float a[4], bq[4];
#pragma unroll
            for (int i = 0; i < 4; i++) a[i] = Kt[r * Ee + ty * 4 + i];
#pragma unroll
            for (int j = 0; j < 4; j++) bq[j] = Vt[r * Ee + tx * 4 + j];
#pragma unroll
            for (int i = 0; i < 4; i++) {
                zacc[i] += a[i];
#pragma unroll
                for (int j = 0; j < 4; j++) acc[i][j] += a[i] * bq[j];
            }
        }
    }
    float* Sd = g_S + (size_t)blk * Ee * Ee;
#pragma unroll
    for (int i = 0; i < 4; i++)
#pragma unroll
        for (int j = 0; j < 4; j++) Sd[(ty * 4 + i) * Ee + tx * 4 + j] = acc[i][j];
    if (tx == 0) {
        float* zd = g_z + (size_t)blk * Ee;
#pragma unroll
        for (int i = 0; i < 4; i++) zd[ty * 4 + i] = zacc[i];
    }
}

// ---------------- K3: exclusive prefix over chunks (full-width grid) ---------
__global__ __launch_bounds__(512) void chunk_prefix_kernel() {
    int bh = blockIdx.x;
    int idx = blockIdx.y * 512 + threadIdx.x;
    float* p = g_S + (size_t)bh * NC * (Ee * Ee) + idx;
    float v[NC];
#pragma unroll
    for (int c = 0; c < NC; c++) v[c] = p[(size_t)c * (Ee * Ee)];
    float carry = 0.f;
#pragma unroll
    for (int c = 0; c < NC; c++) { p[(size_t)c * (Ee * Ee)] = carry; carry += v[c]; }
    if (blockIdx.y == 0 && threadIdx.x < Ee) {
        float* pz = g_z + (size_t)bh * NC * Ee + threadIdx.x;
        float zv[NC];
#pragma unroll
        for (int c = 0; c < NC; c++) zv[c] = pz[c * Ee];
        float zc = 0.f;
#pragma unroll
        for (int c = 0; c < NC; c++) { pz[c * Ee] = zc; zc += zv[c]; }
    }
}

// ---------------- K4: chunked causal linear attention, cp.async pipeline -----
// S+z group first (overlaps q LDG), K/V tiles double-buffered under compute.
__global__ __launch_bounds__(128) void attn_kernel() {
    __shared__ __align__(16) float sS[Ee * Ee];       // 16 KB
    __shared__ __align__(16) float sz[Ee];
    __shared__ __align__(16) float sK[2][32 * Ee];    // 8 KB x2
    __shared__ __align__(16) float sV[2][32 * Ee];    // 8 KB x2
    int blk = blockIdx.x;
    int c = blk & 31;
    int bh = blk >> 5;
    int t = threadIdx.x;
    int wid = t >> 5;
    const float* Kb = g_k + ((size_t)bh * Lq + c * CS) * Ee;
    const float* Vb = g_v + ((size_t)bh * Lq + c * CS) * Ee;
    uint32_t ssb = smem_u32(sS), szb = smem_u32(sz);
    uint32_t ksb = smem_u32(sK), vsb = smem_u32(sV);

    // group 1: S + z
    {
        const float4* Sp = (const float4*)(g_S + (size_t)blk * (Ee * Ee));
#pragma unroll
        for (int u = 0; u < 8; u++)
            CP_ASYNC16(ssb + (uint32_t)((t + u * 128) * 16), Sp + t + u * 128);
        if (t < 16)
            CP_ASYNC16(szb + (uint32_t)(t * 16), (const float4*)(g_z + (size_t)blk * Ee) + t);
        CP_COMMIT();
    }
    auto prefetch = [&](int st, int s0) {
#pragma unroll
        for (int u = 0; u < 4; u++) {
            int idx = t + u * 128;   // 512 float4 each
            CP_ASYNC16(ksb + (uint32_t)(st * 8192 + idx * 16),
                       (const float4*)(Kb + s0 * Ee) + idx);
            CP_ASYNC16(vsb + (uint32_t)(st * 8192 + idx * 16),
                       (const float4*)(Vb + s0 * Ee) + idx);
        }
        CP_COMMIT();
    };
    prefetch(0, 0);                                  // group 2: tile 0

    // q load overlaps the async copies
    const float* qp = g_q + ((size_t)bh * Lq + c * CS + t) * Ee;
    float q[Ee];
#pragma unroll
    for (int i = 0; i < 16; i++) {
        float4 v4 = ((const float4*)qp)[i];
        q[4 * i] = v4.x; q[4 * i + 1] = v4.y; q[4 * i + 2] = v4.z; q[4 * i + 3] = v4.w;
    }

    CP_WAIT(1);                                      // S+z ready (tile 0 in flight)
    __syncthreads();

    float num[Ee];
#pragma unroll
    for (int f = 0; f < Ee; f++) num[f] = 0.f;
    float den = 1e-6f;
#pragma unroll
    for (int e = 0; e < Ee; e++) {
        float qe = q[e];
        den += qe * sz[e];
        const float4* srow = (const float4*)(sS + e * Ee);
#pragma unroll
        for (int f4 = 0; f4 < 16; f4++) {
            float4 sv = srow[f4];
            num[4 * f4]     += qe * sv.x;
            num[4 * f4 + 1] += qe * sv.y;
            num[4 * f4 + 2] += qe * sv.z;
            num[4 * f4 + 3] += qe * sv.w;
        }
    }

    for (int t0 = 0; t0 < 4; t0++) {
        CP_WAIT(0);
        __syncthreads();                              // tile t0 visible; old buffer free
        if (t0 + 1 < 4) prefetch((t0 + 1) & 1, (t0 + 1) * 32);
        if (t0 <= wid) {                              // warp-uniform skip above diagonal
            const float* Kt = sK[t0 & 1];
            const float* Vt = sV[t0 & 1];
            for (int s = 0; s < 32; s++) {
                if (t0 * 32 + s <= t) {
                    float a = 0.f;
                    const float4* krow = (const float4*)(Kt + s * Ee);
#pragma unroll
                    for (int e4 = 0; e4 < 16; e4++) {
                        float4 kv = krow[e4];
                        a += q[4 * e4] * kv.x + q[4 * e4 + 1] * kv.y
                           + q[4 * e4 + 2] * kv.z + q[4 * e4 + 3] * kv.w;
                    }
                    den += a;
                    const float4* vrow = (const float4*)(Vt + s * Ee);
#pragma unroll
                    for (int f4 = 0; f4 < 16; f4++) {
                        float4 vv = vrow[f4];
                        num[4 * f4]     += a * vv.x;
                        num[4 * f4 + 1] += a * vv.y;
                        num[4 * f4 + 2] += a * vv.z;
                        num[4 * f4 + 3] += a * vv.w;
                    }
                }
            }
        }
    }
    float invd = 1.0f / den;
    int b = bh >> 3, h = bh & 7;
    size_t off = ((size_t)(b * Lq + c * CS + t)) * Dm + h * Ee;
    __half2* oh = (__half2*)(g_a16 + off);
#pragma unroll
    for (int f2 = 0; f2 < 32; f2++)
        oh[f2] = __floats2half2_rn(num[2 * f2] * invd, num[2 * f2 + 1] * invd);
}

// ---------------- K6: RMSNorm, warp-per-row -----------------------------------
__global__ __launch_bounds__(256) void rmsnorm_kernel(const float* __restrict__ scale,
                                                      float* __restrict__ out) {
    int w = (blockIdx.x * blockDim.x + threadIdx.x) >> 5;   // row 0..8191
    int lane = threadIdx.x & 31;
    const float4* r = (const float4*)(g_out2 + (size_t)w * Dm);
    float4 v[4];
    float ss = 0.f;
#pragma unroll
    for (int i = 0; i < 4; i++) {
        v[i] = r[lane + 32 * i];
        ss += v[i].x * v[i].x + v[i].y * v[i].y + v[i].z * v[i].z + v[i].w * v[i].w;
    }
#pragma unroll
    for (int o = 16; o; o >>= 1) ss += __shfl_xor_sync(0xffffffffu, ss, o);
    float rn = rsqrtf(ss * (1.0f / 512.0f) + 1e-8f);
    const float4* sc = (const float4*)scale;
    float4* od = (float4*)(out + (size_t)w * Dm);
#pragma unroll
    for (int i = 0; i < 4; i++) {
        float4 s4 = sc[lane + 32 * i];
        float4 o4;
        o4.x = v[i].x * rn * s4.x; o4.y = v[i].y * rn * s4.y;
        o4.z = v[i].z * rn * s4.z; o4.w = v[i].w * rn * s4.w;
        od[lane + 32 * i] = o4;
    }
}

// ---------------- launch ------------------------------------------------------
extern "C" void kernel_launch(void* const* d_in, const int* in_sizes, int n_in,
                              void* d_out, int out_size) {
    const float* x          = (const float*)d_in[0];
    const float* qkv_w      = (const float*)d_in[1];
    const float* qkv_b      = (const float*)d_in[2];
    const float* out_w      = (const float*)d_in[3];
    const float* out_b      = (const float*)d_in[4];
    const float* decay_w    = (const float*)d_in[5];
    const float* decay_b    = (const float*)d_in[6];
    const float* norm_scale = (const float*)d_in[7];
    float* out = (float*)d_out;
    (void)in_sizes; (void)n_in; (void)out_size;

    // dynamic smem: max(3 stages x 16 KB = 49152, C staging 34816)
    const int DYN = 49152;
    static bool attr_set = false;
    if (!attr_set) {
        cudaFuncSetAttribute(gemm_mma_kernel<1>, cudaFuncAttributeMaxDynamicSharedMemorySize, DYN);
        cudaFuncSetAttribute(gemm_mma_kernel<0>, cudaFuncAttributeMaxDynamicSharedMemorySize, DYN);
        attr_set = true;
    }

    split_w_kernel<<<1024, 256>>>(qkv_w, out_w);
    split_x_decay_kernel<<<512, 256>>>(x, decay_w, decay_b);
    cum_scan_kernel<<<BHn, 512>>>();

    gemm_mma_kernel<1><<<dim3(24, 64), 256, DYN>>>(qkv_b);

    chunk_sum_kernel<<<BHn * NC, 256>>>();
    chunk_prefix_kernel<<<dim3(BHn, 8), 512>>>();
    attn_kernel<<<BHn * NC, 128>>>();

    gemm_mma_kernel<0><<<dim3(8, 64), 256, DYN>>>(out_b);

    rmsnorm_kernel<<<1024, 256>>>(norm_scale, out);
}